// round 6
// baseline (speedup 1.0000x reference)
#include <cuda_runtime.h>
#include <cuda_bf16.h>

// Net_33294586479043 — TERMINAL KERNEL.
//
// The network is a 2-layer GCN whose final layer has out_features=1, followed
// by log_softmax(axis=1) over a [N, 1] tensor. log_softmax on a size-1 axis
// is identically 0.0f (stable form: 0 - log(exp(0)) = -log(1) = 0, exact in
// fp32). The entire graph convolution (both SpMMs over 1.6M edges) is dead
// code; the reference output is 100,000 exact zeros. rel_err = 0.0 confirmed
// across 5 benches.
//
// Minimum work: zero-fill 400KB of d_out (harness poisons it to 0xAA).
// Measured landscape (total / kernel, us):
//   R1 grid-stride 1xSTG.128/thread, 98x256 : 4.58 / 3.39   <- this source
//   R2 2 stores/thread, 49 blocks           : 5.47 / 3.87
//   R3 straight-line 1 store/thread         : 5.22 / 3.65
//   R4 graph memset node (cudaMemsetAsync)  : 6.88 /  —
//   R5 re-bench of R1 (control)             : 4.86 / 3.68
// Identical source spans 4.58-4.86us => run-to-run noise ~±0.3us. The kernel
// sits at the single-node graph-replay + launch-ramp floor: 400KB of stores
// is ~50ns of DRAM time (ncu: DRAM 0.0%, issue ~5%). No lever remains below
// the launch floor; further shape changes only sample noise.

__global__ void zero_out_kernel(float4* __restrict__ out4, int n4,
                                float* __restrict__ out_tail, int tail_start, int n) {
    int i = blockIdx.x * blockDim.x + threadIdx.x;
    const float4 z = make_float4(0.f, 0.f, 0.f, 0.f);
    // grid-stride over float4 body (single iteration at the launched grid)
    for (int idx = i; idx < n4; idx += gridDim.x * blockDim.x) {
        out4[idx] = z;
    }
    // defensive tail (0..3 elements); no-op for out_size % 4 == 0
    if (i == 0) {
        for (int t = tail_start; t < n; ++t) out_tail[t] = 0.0f;
    }
}

extern "C" void kernel_launch(void* const* d_in, const int* in_sizes, int n_in,
                              void* d_out, int out_size) {
    (void)d_in; (void)in_sizes; (void)n_in;
    float* out = (float*)d_out;
    int n = out_size;          // 100000 expected
    int n4 = n / 4;            // 25000 float4 stores
    int tail_start = n4 * 4;

    int threads = 256;
    int blocks = (n4 + threads - 1) / threads;   // 98 for n=100000
    if (blocks < 1) blocks = 1;

    zero_out_kernel<<<blocks, threads>>>((float4*)out, n4, out, tail_start, n);
}